// round 11
// baseline (speedup 1.0000x reference)
#include <cuda_runtime.h>
#include <cuda_bf16.h>

#define HIDDEN   64
#define SEQ_LEN  128
#define BATCH    64
#define NPTS     (BATCH * SEQ_LEN)   // 8192
#define T_MAX_V  20.0f
#define KTERMS   40
#define NBLK_B   256                 // reward grid
#define NTHR_B   256

// ---------------- device scratch ----------------
__device__ float  g_lc[NPTS];
__device__ int    g_nl = 0;          // reset by finalize each run (graph-safe)
__device__ float  g_llp[NBLK_B];
__device__ double g_Me[KTERMS];
__device__ double g_Ml[KTERMS];

// c_k = 2^k / k!
__constant__ double c_coef[KTERMS] = {
    1.0, 2.0, 2.0, 1.3333333333333333, 0.6666666666666666,
    0.26666666666666666, 0.08888888888888889, 0.025396825396825397,
    0.006349206349206349, 0.0014109347442680775, 2.821869488536155e-04,
    5.130671797338464e-05, 8.551119662230773e-06, 1.3155568711124266e-06,
    1.8793669587320378e-07, 2.505822611642717e-08, 3.132278264553396e-09,
    3.6850332524157603e-10, 4.0944813915730673e-11, 4.3099804121822816e-12,
    4.3099804121822815e-13, 4.104743249697411e-14, 3.7315847724521917e-15,
    3.244856323871471e-16, 2.7040469365595593e-17, 2.1632375492476474e-18,
    1.6640288840366519e-19, 1.2326139881753718e-20, 8.804385629824085e-22,
    6.072024572292472e-23, 4.048016381528315e-24, 2.6116234719537516e-25,
    1.6322646699710948e-26, 9.892513151339969e-28, 5.819125383141158e-29,
    3.325214504652090e-30, 1.847341391473383e-31, 9.985629143099369e-33,
    5.255594285841772e-34, 2.695176556841934e-35
};

// ---------------- helpers ----------------
__device__ __forceinline__ unsigned long long pk2(float lo, float hi) {
    unsigned long long u;
    asm("mov.b64 %0, {%1, %2};" : "=l"(u) : "f"(lo), "f"(hi));
    return u;
}
__device__ __forceinline__ void upk2(unsigned long long u, float& lo, float& hi) {
    asm("mov.b64 {%0, %1}, %2;" : "=f"(lo), "=f"(hi) : "l"(u));
}
#define FFMA2(acc, a, b) \
    asm("fma.rn.f32x2 %0, %1, %2, %0;" : "+l"(acc) : "l"(a), "l"(b))
#define FADD2(dst, a, b) \
    asm("add.rn.f32x2 %0, %1, %2;" : "=l"(dst) : "l"(a), "l"(b))

__device__ __forceinline__ float tanh_apx(float x) {
    float y;
    asm("tanh.approx.f32 %0, %1;" : "=f"(y) : "f"(x));
    return y;
}

// moment accumulation helper (per-thread partial for fixed k)
__device__ __forceinline__ float moment_partial(const float* __restrict__ src,
                                                int n, int k, int tid, int stride) {
    float macc = 0.f;
    for (int p = tid; p < n; p += stride) {
        float t = src[p];
        bool ok = (t > 0.f) && (t < 8.f);     // beyond 8: exp(-t^2) < e^-64
        float wp = ok ? __expf(-t * t) : 0.f;
        float base = ok ? t : 0.f;            // keep base finite -> no 0*Inf
        int kk = k;
        while (kk) { if (kk & 1) wp *= base; base *= base; kk >>= 1; }
        macc += wp;
    }
    return macc;
}

// ================= kernel 1: rollout (104 blocks x 256) =================
// Blocks 0-63: LSTM rollout, one batch each.
//   Warp w, lane l owns matvec row gate*64 + w*8 + u (gate=l>>3, u=l&7).
//   Gate activations are exchanged with 3 parallel shuffles. hv is folded
//   8 -> 2 with TWO shuffles (lanes 0,1 store -> 16 slots total); the
//   redundant-per-warp sigma chain sums ALL 16 slots with packed f32x2 adds
//   (R10 bug: it summed only 16 of 32 slots = half the hidden state).
//   One barrier per step; hx/hv double-buffered on step parity.
// Blocks 64-103: expert moment k = blockIdx-64 on otherwise-idle SMs.
__global__ void __launch_bounds__(256, 1)
pp_rollout_kernel(const float* __restrict__ pool,
                  const float* __restrict__ Wih,
                  const float* __restrict__ Whh,
                  const float* __restrict__ bih,
                  const float* __restrict__ bhh,
                  const float* __restrict__ Vw,
                  const float* __restrict__ Vb,
                  const float* __restrict__ et) {
    const int bk   = blockIdx.x;
    const int tid  = threadIdx.x;
    const int w    = tid >> 5;
    const int l    = tid & 31;

    // ---------- expert moment blocks ----------
    if (bk >= BATCH) {
        const int k = bk - BATCH;     // 0..39
        float macc = moment_partial(et, NPTS, k, tid, 256);
        __shared__ float msum[8];
#pragma unroll
        for (int o = 16; o > 0; o >>= 1) macc += __shfl_xor_sync(0xffffffffu, macc, o);
        if (l == 0) msum[w] = macc;
        __syncthreads();
        if (tid == 0) {
            double s = (double)((msum[0] + msum[1]) + (msum[2] + msum[3]))
                     + (double)((msum[4] + msum[5]) + (msum[6] + msum[7]));
            g_Me[k] = s;
        }
        return;
    }

    // ---------- rollout blocks ----------
    const int b    = bk;
    const int gate = l >> 3;          // 0=i 1=f 2=g 3=o
    const int ug   = l & 7;           // unit within warp's group
    const int row  = gate * 64 + w * 8 + ug;

    __shared__ __align__(16) float hx_sb[2][HIDDEN];
    __shared__ __align__(16) float hv_sb[2][16];
    __shared__ __align__(16) float lg_s[SEQ_LEN];
    __shared__ __align__(16) float cum_hist[SEQ_LEN];

    // preload W_hh row as packed f32x2
    unsigned long long w2[32];
    {
        const float4* wrow = (const float4*)(Whh + row * HIDDEN);
#pragma unroll
        for (int q = 0; q < 16; q++) {
            float4 v = wrow[q];
            w2[2 * q]     = pk2(v.x, v.y);
            w2[2 * q + 1] = pk2(v.z, v.w);
        }
    }
    const float wih  = Wih[row];
    const float bias = bih[row] + bhh[row];
    const float vb   = Vb[0];
    const bool  isg  = (gate == 2);
    const float vw   = (l < 8) ? Vw[w * 8 + l] : 0.f;

    if (tid < HIDDEN) hx_sb[0][tid] = 0.f;
    if (tid < 16)     hv_sb[0][tid] = 0.f;
    if (tid < SEQ_LEN) lg_s[tid] = -__logf(pool[b * SEQ_LEN + tid]);

    float cx = 0.f;       // lanes 0..7: cell state of unit w*8+l
    float cum_v = 0.f;    // redundant in every lane of every warp
    __syncthreads();

    for (int s = 0; s < SEQ_LEN; s++) {
        const int p = s & 1;

        // ---- cum/sigma chain (redundant per warp; parallel to matvec) ----
        // sum ALL 16 hv partials (4 x LDS.128, 7 packed FADD2, depth 3)
        const ulonglong2* hv4 = (const ulonglong2*)hv_sb[p];
        ulonglong2 va = hv4[0], vb2 = hv4[1], vc = hv4[2], vd = hv4[3];
        unsigned long long s1, s2, s3, s4, s5, s6, s7;
        FADD2(s1, va.x, va.y);
        FADD2(s2, vb2.x, vb2.y);
        FADD2(s3, vc.x, vc.y);
        FADD2(s4, vd.x, vd.y);
        FADD2(s5, s1, s2);
        FADD2(s6, s3, s4);
        FADD2(s7, s5, s6);
        float slo, shi;
        upk2(s7, slo, shi);
        float S = slo + shi;
        float z = S + vb;
        float sigma = (z > 0.f ? z : (__expf(z) - 1.f)) + 1.f;   // elu + 1
        cum_v += __fdividef(lg_s[s], sigma);

        // ---- matvec row: m = bias + Whh[row,:] @ hx ----
        unsigned long long acc0 = pk2(bias, 0.f);
        unsigned long long acc1 = 0ull, acc2 = 0ull, acc3 = 0ull;
        const ulonglong2* h4 = (const ulonglong2*)hx_sb[p];
#pragma unroll
        for (int j = 0; j < 8; j++) {
            ulonglong2 ha = h4[2 * j];
            ulonglong2 hb = h4[2 * j + 1];
            FFMA2(acc0, w2[4 * j + 0], ha.x);
            FFMA2(acc1, w2[4 * j + 1], ha.y);
            FFMA2(acc2, w2[4 * j + 2], hb.x);
            FFMA2(acc3, w2[4 * j + 3], hb.y);
        }
        unsigned long long p0, p1, pz;
        FADD2(p0, acc0, acc1);
        FADD2(p1, acc2, acc3);
        FADD2(pz, p0, p1);
        float lo, hi;
        upk2(pz, lo, hi);
        float gv = fmaf(cum_v, wih, lo + hi);

        // ---- activation (sigmoid via tanh identity; g-gate plain tanh) ----
        float pre = isg ? gv : 0.5f * gv;
        float tv  = tanh_apx(pre);
        float act = isg ? tv : fmaf(tv, 0.5f, 0.5f);

        // ---- gather gates to unit lanes (3 parallel shuffles) ----
        float fv = __shfl_sync(0xffffffffu, act, ug + 8);
        float gg = __shfl_sync(0xffffffffu, act, ug + 16);
        float ov = __shfl_sync(0xffffffffu, act, ug + 24);

        float hv = 0.f;
        if (l < 8) {
            cx = fmaf(fv, cx, act * gg);
            float h = ov * tanh_apx(cx);
            hx_sb[p ^ 1][w * 8 + l] = h;
            hv = h * vw;
        }
        // fold 8 -> 2 with two shuffles; lanes 0,1 store (16 slots total)
        hv += __shfl_xor_sync(0xffffffffu, hv, 4);
        hv += __shfl_xor_sync(0xffffffffu, hv, 2);
        if (l < 2) hv_sb[p ^ 1][w * 2 + l] = hv;
        if (tid == 0) cum_hist[s] = cum_v;
        __syncthreads();
    }

    // ---------------- epilogue: compaction of valid times ----------------
    if (tid < SEQ_LEN) {
        float t = cum_hist[tid];
        bool valid = (t > 0.f) && (t < T_MAX_V);
        unsigned bal = __ballot_sync(0xffffffffu, valid);
        int base = 0;
        if (l == 0) base = atomicAdd(&g_nl, __popc(bal));
        base = __shfl_sync(0xffffffffu, base, 0);
        if (valid) g_lc[base + __popc(bal & ((1u << l) - 1u))] = t;
    }
}

// ================= kernel 2: reward (256 blocks x 256) =================
// All blocks: symmetric ll pair partial -> g_llp[bk] (distinct slots, no atomics).
// Blocks 0-39: learner moment k (expert moments were done in kernel 1).
__global__ void __launch_bounds__(NTHR_B, 4)
pp_reward_kernel() {
    const int T   = NBLK_B * NTHR_B;
    const int g   = blockIdx.x * NTHR_B + threadIdx.x;
    const int bk  = blockIdx.x;
    const int tid = threadIdx.x;
    const int wrp = tid >> 5, lane = tid & 31;
    const int nl  = g_nl;

    // ---- ll pair sum (j > i, symmetric) ----
    float acc = 0.f;
    if (nl > 0) {
        const int R = T / nl;
        if (g < R * nl) {
            const int i  = g % nl;
            const int r0 = g / nl;
            const float ti = g_lc[i];
            for (int j = i + 1 + r0; j < nl; j += R) {
                float d = ti - g_lc[j];
                acc += __expf(-d * d);
            }
        }
    }
    __shared__ float bsum[8];
#pragma unroll
    for (int o = 16; o > 0; o >>= 1) acc += __shfl_xor_sync(0xffffffffu, acc, o);
    if (lane == 0) bsum[wrp] = acc;
    __syncthreads();
    if (tid == 0) {
        float s = ((bsum[0] + bsum[1]) + (bsum[2] + bsum[3]))
                + ((bsum[4] + bsum[5]) + (bsum[6] + bsum[7]));
        g_llp[bk] = s;
    }

    // ---- learner moment blocks ----
    if (bk < KTERMS) {
        float macc = moment_partial(g_lc, nl, bk, tid, NTHR_B);
        __shared__ float msum[8];
#pragma unroll
        for (int o = 16; o > 0; o >>= 1) macc += __shfl_xor_sync(0xffffffffu, macc, o);
        if (lane == 0) msum[wrp] = macc;
        __syncthreads();
        if (tid == 0) {
            double s = (double)((msum[0] + msum[1]) + (msum[2] + msum[3]))
                     + (double)((msum[4] + msum[5]) + (msum[6] + msum[7]));
            g_Ml[bk] = s;
        }
    }
}

// ================= kernel 3: finalize (1 block x 256) =================
__global__ void __launch_bounds__(NTHR_B, 1)
pp_finalize_kernel(float* __restrict__ out) {
    const int tid = threadIdx.x;
    const int wrp = tid >> 5, lane = tid & 31;

    double d = (double)g_llp[tid];
#pragma unroll
    for (int o = 16; o > 0; o >>= 1) d += __shfl_xor_sync(0xffffffffu, d, o);
    __shared__ double wsum[8];
    if (lane == 0) wsum[wrp] = d;

    __shared__ double t_ee[KTERMS], t_le[KTERMS];
    if (tid < KTERMS) {
        double c  = c_coef[tid];
        double me = g_Me[tid];
        t_ee[tid] = c * me * me;
        t_le[tid] = c * me * g_Ml[tid];
    }
    __syncthreads();

    if (tid == 0) {
        double llp = ((wsum[0] + wsum[1]) + (wsum[2] + wsum[3]))
                   + ((wsum[4] + wsum[5]) + (wsum[6] + wsum[7]));
        double e0 = 0, e1 = 0, e2 = 0, e3 = 0, l0 = 0, l1 = 0, l2 = 0, l3 = 0;
#pragma unroll
        for (int k = 0; k < KTERMS; k += 4) {
            e0 += t_ee[k]; e1 += t_ee[k + 1]; e2 += t_ee[k + 2]; e3 += t_ee[k + 3];
            l0 += t_le[k]; l1 += t_le[k + 1]; l2 += t_le[k + 2]; l3 += t_le[k + 3];
        }
        double ee = (e0 + e1) + (e2 + e3);
        double le = (l0 + l1) + (l2 + l3);
        double ll = 2.0 * llp + (double)g_nl;   // off-diag*2 + diagonal
        out[0] = (float)(ee + ll - 2.0 * le);
        g_nl = 0;                                // reset for next replay
    }
}

// ---------------- launch ----------------
extern "C" void kernel_launch(void* const* d_in, const int* in_sizes, int n_in,
                              void* d_out, int out_size) {
    const float* pool = (const float*)d_in[0];
    const float* et   = (const float*)d_in[1];
    const float* Wih  = (const float*)d_in[2];
    const float* Whh  = (const float*)d_in[3];
    const float* bih  = (const float*)d_in[4];
    const float* bhh  = (const float*)d_in[5];
    const float* Vw   = (const float*)d_in[6];
    const float* Vb   = (const float*)d_in[7];
    float* out = (float*)d_out;

    pp_rollout_kernel<<<BATCH + KTERMS, 256>>>(pool, Wih, Whh, bih, bhh, Vw, Vb, et);
    pp_reward_kernel<<<NBLK_B, NTHR_B>>>();
    pp_finalize_kernel<<<1, NTHR_B>>>(out);
}

// round 12
// speedup vs baseline: 1.5268x; 1.5268x over previous
#include <cuda_runtime.h>
#include <cuda_bf16.h>

#define HIDDEN   64
#define SEQ_LEN  128
#define BATCH    64
#define NPTS     (BATCH * SEQ_LEN)   // 8192
#define T_MAX_V  20.0f
#define KTERMS   40
#define NBLK_B   256                 // reward grid
#define NTHR_B   256

// ---------------- device scratch ----------------
__device__ float  g_lc[NPTS];
__device__ int    g_nl = 0;          // reset by finalize each run (graph-safe)
__device__ float  g_llp[NBLK_B];
__device__ double g_Me[KTERMS];
__device__ double g_Ml[KTERMS];

// c_k = 2^k / k!
__constant__ double c_coef[KTERMS] = {
    1.0, 2.0, 2.0, 1.3333333333333333, 0.6666666666666666,
    0.26666666666666666, 0.08888888888888889, 0.025396825396825397,
    0.006349206349206349, 0.0014109347442680775, 2.821869488536155e-04,
    5.130671797338464e-05, 8.551119662230773e-06, 1.3155568711124266e-06,
    1.8793669587320378e-07, 2.505822611642717e-08, 3.132278264553396e-09,
    3.6850332524157603e-10, 4.0944813915730673e-11, 4.3099804121822816e-12,
    4.3099804121822815e-13, 4.104743249697411e-14, 3.7315847724521917e-15,
    3.244856323871471e-16, 2.7040469365595593e-17, 2.1632375492476474e-18,
    1.6640288840366519e-19, 1.2326139881753718e-20, 8.804385629824085e-22,
    6.072024572292472e-23, 4.048016381528315e-24, 2.6116234719537516e-25,
    1.6322646699710948e-26, 9.892513151339969e-28, 5.819125383141158e-29,
    3.325214504652090e-30, 1.847341391473383e-31, 9.985629143099369e-33,
    5.255594285841772e-34, 2.695176556841934e-35
};

// ---------------- helpers ----------------
__device__ __forceinline__ unsigned long long pk2(float lo, float hi) {
    unsigned long long u;
    asm("mov.b64 %0, {%1, %2};" : "=l"(u) : "f"(lo), "f"(hi));
    return u;
}
__device__ __forceinline__ void upk2(unsigned long long u, float& lo, float& hi) {
    asm("mov.b64 {%0, %1}, %2;" : "=f"(lo), "=f"(hi) : "l"(u));
}
#define FFMA2(acc, a, b) \
    asm("fma.rn.f32x2 %0, %1, %2, %0;" : "+l"(acc) : "l"(a), "l"(b))
#define FADD2(dst, a, b) \
    asm("add.rn.f32x2 %0, %1, %2;" : "=l"(dst) : "l"(a), "l"(b))

__device__ __forceinline__ float tanh_apx(float x) {
    float y;
    asm("tanh.approx.f32 %0, %1;" : "=f"(y) : "f"(x));
    return y;
}

// moment accumulation helper (per-thread partial for fixed k)
__device__ __forceinline__ float moment_partial(const float* __restrict__ src,
                                                int n, int k, int tid, int stride) {
    float macc = 0.f;
    for (int p = tid; p < n; p += stride) {
        float t = src[p];
        bool ok = (t > 0.f) && (t < 8.f);     // beyond 8: exp(-t^2) < e^-64
        float wp = ok ? __expf(-t * t) : 0.f;
        float base = ok ? t : 0.f;            // keep base finite -> no 0*Inf
        int kk = k;
        while (kk) { if (kk & 1) wp *= base; base *= base; kk >>= 1; }
        macc += wp;
    }
    return macc;
}

// ================= kernel 1: rollout (104 blocks x 256) =================
// Blocks 0-63: LSTM rollout, one batch each (exact R10 loop structure, which
//   measured fastest: single-shuffle hv fold, lanes 0-3 store -> 32 slots).
//   BUG FIX vs R10: the sigma chain now reads ALL 32 slots (8 x LDS.128,
//   15 packed FADD2) instead of 16, so S covers the full hidden state.
// Blocks 64-103: expert moment k = blockIdx-64 on otherwise-idle SMs.
__global__ void __launch_bounds__(256, 1)
pp_rollout_kernel(const float* __restrict__ pool,
                  const float* __restrict__ Wih,
                  const float* __restrict__ Whh,
                  const float* __restrict__ bih,
                  const float* __restrict__ bhh,
                  const float* __restrict__ Vw,
                  const float* __restrict__ Vb,
                  const float* __restrict__ et) {
    const int bk   = blockIdx.x;
    const int tid  = threadIdx.x;
    const int w    = tid >> 5;
    const int l    = tid & 31;

    // ---------- expert moment blocks ----------
    if (bk >= BATCH) {
        const int k = bk - BATCH;     // 0..39
        float macc = moment_partial(et, NPTS, k, tid, 256);
        __shared__ float msum[8];
#pragma unroll
        for (int o = 16; o > 0; o >>= 1) macc += __shfl_xor_sync(0xffffffffu, macc, o);
        if (l == 0) msum[w] = macc;
        __syncthreads();
        if (tid == 0) {
            double s = (double)((msum[0] + msum[1]) + (msum[2] + msum[3]))
                     + (double)((msum[4] + msum[5]) + (msum[6] + msum[7]));
            g_Me[k] = s;
        }
        return;
    }

    // ---------- rollout blocks ----------
    const int b    = bk;
    const int gate = l >> 3;          // 0=i 1=f 2=g 3=o
    const int ug   = l & 7;           // unit within warp's group
    const int row  = gate * 64 + w * 8 + ug;

    __shared__ __align__(16) float hx_sb[2][HIDDEN];
    __shared__ __align__(16) float hv_sb[2][32];
    __shared__ __align__(16) float lg_s[SEQ_LEN];
    __shared__ __align__(16) float cum_hist[SEQ_LEN];

    // preload W_hh row as packed f32x2
    unsigned long long w2[32];
    {
        const float4* wrow = (const float4*)(Whh + row * HIDDEN);
#pragma unroll
        for (int q = 0; q < 16; q++) {
            float4 v = wrow[q];
            w2[2 * q]     = pk2(v.x, v.y);
            w2[2 * q + 1] = pk2(v.z, v.w);
        }
    }
    const float wih  = Wih[row];
    const float bias = bih[row] + bhh[row];
    const float vb   = Vb[0];
    const bool  isg  = (gate == 2);
    const float vw   = (l < 8) ? Vw[w * 8 + l] : 0.f;

    if (tid < HIDDEN) hx_sb[0][tid] = 0.f;
    if (tid < 32)     hv_sb[0][tid] = 0.f;
    if (tid < SEQ_LEN) lg_s[tid] = -__logf(pool[b * SEQ_LEN + tid]);

    float cx = 0.f;       // lanes 0..7: cell state of unit w*8+l
    float cum_v = 0.f;    // redundant in every lane of every warp
    __syncthreads();

    for (int s = 0; s < SEQ_LEN; s++) {
        const int p = s & 1;

        // ---- cum/sigma chain (redundant per warp; parallel to matvec) ----
        // sum ALL 32 hv partials: 8 x LDS.128 + 15 packed FADD2 (depth 4)
        const ulonglong2* hv4 = (const ulonglong2*)hv_sb[p];
        ulonglong2 va = hv4[0], vb2 = hv4[1], vc = hv4[2], vd = hv4[3];
        ulonglong2 ve = hv4[4], vf = hv4[5], vg = hv4[6], vh = hv4[7];
        unsigned long long t1, t2, t3, t4, t5, t6, t7, t8;
        FADD2(t1, va.x, va.y);
        FADD2(t2, vb2.x, vb2.y);
        FADD2(t3, vc.x, vc.y);
        FADD2(t4, vd.x, vd.y);
        FADD2(t5, ve.x, ve.y);
        FADD2(t6, vf.x, vf.y);
        FADD2(t7, vg.x, vg.y);
        FADD2(t8, vh.x, vh.y);
        unsigned long long u1, u2, u3, u4, u5, u6, u7;
        FADD2(u1, t1, t2);
        FADD2(u2, t3, t4);
        FADD2(u3, t5, t6);
        FADD2(u4, t7, t8);
        FADD2(u5, u1, u2);
        FADD2(u6, u3, u4);
        FADD2(u7, u5, u6);
        float slo, shi;
        upk2(u7, slo, shi);
        float S = slo + shi;
        float z = S + vb;
        float sigma = (z > 0.f ? z : (__expf(z) - 1.f)) + 1.f;   // elu + 1
        cum_v += __fdividef(lg_s[s], sigma);

        // ---- matvec row: m = bias + Whh[row,:] @ hx ----
        unsigned long long acc0 = pk2(bias, 0.f);
        unsigned long long acc1 = 0ull, acc2 = 0ull, acc3 = 0ull;
        const ulonglong2* h4 = (const ulonglong2*)hx_sb[p];
#pragma unroll
        for (int j = 0; j < 8; j++) {
            ulonglong2 ha = h4[2 * j];
            ulonglong2 hb = h4[2 * j + 1];
            FFMA2(acc0, w2[4 * j + 0], ha.x);
            FFMA2(acc1, w2[4 * j + 1], ha.y);
            FFMA2(acc2, w2[4 * j + 2], hb.x);
            FFMA2(acc3, w2[4 * j + 3], hb.y);
        }
        unsigned long long p0, p1, pz;
        FADD2(p0, acc0, acc1);
        FADD2(p1, acc2, acc3);
        FADD2(pz, p0, p1);
        float lo, hi;
        upk2(pz, lo, hi);
        float gv = fmaf(cum_v, wih, lo + hi);

        // ---- activation (sigmoid via tanh identity; g-gate plain tanh) ----
        float pre = isg ? gv : 0.5f * gv;
        float tv  = tanh_apx(pre);
        float act = isg ? tv : fmaf(tv, 0.5f, 0.5f);

        // ---- gather gates to unit lanes (3 parallel shuffles) ----
        float fv = __shfl_sync(0xffffffffu, act, ug + 8);
        float gg = __shfl_sync(0xffffffffu, act, ug + 16);
        float ov = __shfl_sync(0xffffffffu, act, ug + 24);

        float hv = 0.f;
        if (l < 8) {
            cx = fmaf(fv, cx, act * gg);
            float h = ov * tanh_apx(cx);
            hx_sb[p ^ 1][w * 8 + l] = h;
            hv = h * vw;
        }
        // fold 8 -> 4 with ONE shuffle; lanes 0..3 store (32 slots total)
        hv += __shfl_xor_sync(0xffffffffu, hv, 4);
        if (l < 4) hv_sb[p ^ 1][w * 4 + l] = hv;
        if (tid == 0) cum_hist[s] = cum_v;
        __syncthreads();
    }

    // ---------------- epilogue: compaction of valid times ----------------
    if (tid < SEQ_LEN) {
        float t = cum_hist[tid];
        bool valid = (t > 0.f) && (t < T_MAX_V);
        unsigned bal = __ballot_sync(0xffffffffu, valid);
        int base = 0;
        if (l == 0) base = atomicAdd(&g_nl, __popc(bal));
        base = __shfl_sync(0xffffffffu, base, 0);
        if (valid) g_lc[base + __popc(bal & ((1u << l) - 1u))] = t;
    }
}

// ================= kernel 2: reward (256 blocks x 256) =================
// All blocks: symmetric ll pair partial -> g_llp[bk] (distinct slots, no atomics).
// Blocks 0-39: learner moment k (expert moments were done in kernel 1).
__global__ void __launch_bounds__(NTHR_B, 4)
pp_reward_kernel() {
    const int T   = NBLK_B * NTHR_B;
    const int g   = blockIdx.x * NTHR_B + threadIdx.x;
    const int bk  = blockIdx.x;
    const int tid = threadIdx.x;
    const int wrp = tid >> 5, lane = tid & 31;
    const int nl  = g_nl;

    // ---- ll pair sum (j > i, symmetric) ----
    float acc = 0.f;
    if (nl > 0) {
        const int R = T / nl;
        if (g < R * nl) {
            const int i  = g % nl;
            const int r0 = g / nl;
            const float ti = g_lc[i];
            for (int j = i + 1 + r0; j < nl; j += R) {
                float d = ti - g_lc[j];
                acc += __expf(-d * d);
            }
        }
    }
    __shared__ float bsum[8];
#pragma unroll
    for (int o = 16; o > 0; o >>= 1) acc += __shfl_xor_sync(0xffffffffu, acc, o);
    if (lane == 0) bsum[wrp] = acc;
    __syncthreads();
    if (tid == 0) {
        float s = ((bsum[0] + bsum[1]) + (bsum[2] + bsum[3]))
                + ((bsum[4] + bsum[5]) + (bsum[6] + bsum[7]));
        g_llp[bk] = s;
    }

    // ---- learner moment blocks ----
    if (bk < KTERMS) {
        float macc = moment_partial(g_lc, nl, bk, tid, NTHR_B);
        __shared__ float msum[8];
#pragma unroll
        for (int o = 16; o > 0; o >>= 1) macc += __shfl_xor_sync(0xffffffffu, macc, o);
        if (lane == 0) msum[wrp] = macc;
        __syncthreads();
        if (tid == 0) {
            double s = (double)((msum[0] + msum[1]) + (msum[2] + msum[3]))
                     + (double)((msum[4] + msum[5]) + (msum[6] + msum[7]));
            g_Ml[bk] = s;
        }
    }
}

// ================= kernel 3: finalize (1 block x 256) =================
__global__ void __launch_bounds__(NTHR_B, 1)
pp_finalize_kernel(float* __restrict__ out) {
    const int tid = threadIdx.x;
    const int wrp = tid >> 5, lane = tid & 31;

    double d = (double)g_llp[tid];
#pragma unroll
    for (int o = 16; o > 0; o >>= 1) d += __shfl_xor_sync(0xffffffffu, d, o);
    __shared__ double wsum[8];
    if (lane == 0) wsum[wrp] = d;

    __shared__ double t_ee[KTERMS], t_le[KTERMS];
    if (tid < KTERMS) {
        double c  = c_coef[tid];
        double me = g_Me[tid];
        t_ee[tid] = c * me * me;
        t_le[tid] = c * me * g_Ml[tid];
    }
    __syncthreads();

    if (tid == 0) {
        double llp = ((wsum[0] + wsum[1]) + (wsum[2] + wsum[3]))
                   + ((wsum[4] + wsum[5]) + (wsum[6] + wsum[7]));
        double e0 = 0, e1 = 0, e2 = 0, e3 = 0, l0 = 0, l1 = 0, l2 = 0, l3 = 0;
#pragma unroll
        for (int k = 0; k < KTERMS; k += 4) {
            e0 += t_ee[k]; e1 += t_ee[k + 1]; e2 += t_ee[k + 2]; e3 += t_ee[k + 3];
            l0 += t_le[k]; l1 += t_le[k + 1]; l2 += t_le[k + 2]; l3 += t_le[k + 3];
        }
        double ee = (e0 + e1) + (e2 + e3);
        double le = (l0 + l1) + (l2 + l3);
        double ll = 2.0 * llp + (double)g_nl;   // off-diag*2 + diagonal
        out[0] = (float)(ee + ll - 2.0 * le);
        g_nl = 0;                                // reset for next replay
    }
}

// ---------------- launch ----------------
extern "C" void kernel_launch(void* const* d_in, const int* in_sizes, int n_in,
                              void* d_out, int out_size) {
    const float* pool = (const float*)d_in[0];
    const float* et   = (const float*)d_in[1];
    const float* Wih  = (const float*)d_in[2];
    const float* Whh  = (const float*)d_in[3];
    const float* bih  = (const float*)d_in[4];
    const float* bhh  = (const float*)d_in[5];
    const float* Vw   = (const float*)d_in[6];
    const float* Vb   = (const float*)d_in[7];
    float* out = (float*)d_out;

    pp_rollout_kernel<<<BATCH + KTERMS, 256>>>(pool, Wih, Whh, bih, bhh, Vw, Vb, et);
    pp_reward_kernel<<<NBLK_B, NTHR_B>>>();
    pp_finalize_kernel<<<1, NTHR_B>>>(out);
}